// round 11
// baseline (speedup 1.0000x reference)
#include <cuda_runtime.h>
#include <math.h>

#define NV 50257
#define NE 256
#define NC 48
#define NB 64
#define NT 1024
#define HT 512

#define LOG48    3.8712010109078911f
#define T1_LOG48 3960.2386341588226f   /* 1023 * log(48) */

// packed f32x2 helpers (Blackwell: fma/add/mul .rn.f32x2, 64-bit regs)
#define FMA2(acc, a, b) asm("fma.rn.f32x2 %0, %1, %2, %0;" : "+l"(acc) : "l"(a), "l"(b))
#define ADD2(a, b)      asm("add.rn.f32x2 %0, %0, %1;"     : "+l"(a)   : "l"(b))
#define MUL2(d, a, b)   asm("mul.rn.f32x2 %0, %1, %2;"     : "=l"(d)   : "l"(a), "l"(b))
__device__ __forceinline__ unsigned long long pack2(float lo, float hi) {
    unsigned long long r;
    asm("mov.b64 %0, {%1, %2};" : "=l"(r) : "r"(__float_as_uint(lo)), "r"(__float_as_uint(hi)));
    return r;
}
__device__ __forceinline__ unsigned long long bcast2(float v) {
    unsigned long long r;
    asm("mov.b64 %0, {%1, %1};" : "=l"(r) : "r"(__float_as_uint(v)));
    return r;
}
__device__ __forceinline__ float hadd2(unsigned long long a) {
    unsigned lo, hi;
    asm("mov.b64 {%0, %1}, %2;" : "=r"(lo), "=r"(hi) : "l"(a));
    return __uint_as_float(lo) + __uint_as_float(hi);
}
__device__ __forceinline__ float2 unpk2(unsigned long long a) {
    unsigned lo, hi;
    asm("mov.b64 {%0, %1}, %2;" : "=r"(lo), "=r"(hi) : "l"(a));
    return make_float2(__uint_as_float(lo), __uint_as_float(hi));
}

// Scratch (static device globals — no runtime allocation)
__device__ float g_P[NV * NC];        // emb_table @ fc_w^T + fc_b  (9.65 MB)
__device__ float g_ab[2][NB][NC];     // [0]=alpha_mid (fwd), [1]=beta_mid (bwd)
__device__ float g_num[2 * NB];       // per-block partial numerator
__device__ unsigned g_ctr;            // crf2 completion counter (reset by last block)

// ---------------------------------------------------------------------------
// K1: P[v, c] = sum_e emb[v, e] * fcw[c, e] + fcb[c]   (unchanged, ~25 µs)
// ---------------------------------------------------------------------------
__global__ __launch_bounds__(256)
void k_gemm(const float* __restrict__ emb, const float* __restrict__ fcw,
            const float* __restrict__ fcb) {
    __shared__ __align__(16) float Ws[NE * NC];   // 48 KB, k-major
    const int tid = threadIdx.x;
    const int m0 = blockIdx.x * 128;

    for (int idx = tid; idx < NC * NE; idx += 256) {
        int c = idx >> 8, k = idx & 255;
        Ws[k * NC + c] = fcw[idx];
    }
    __syncthreads();

    const int i = tid >> 2;
    const int q = tid & 3;
    const int row0 = m0 + i;
    const int row1 = m0 + 64 + i;
    const bool v0 = row0 < NV, v1 = row1 < NV;
    const float4* A0 = (const float4*)emb + (size_t)(v0 ? row0 : NV - 1) * 64;
    const float4* A1 = (const float4*)emb + (size_t)(v1 ? row1 : NV - 1) * 64;
    const unsigned long long* Wq = (const unsigned long long*)Ws + q * 6;

    unsigned long long c0[6], c1[6];
#pragma unroll
    for (int j = 0; j < 6; j++) { c0[j] = 0ull; c1[j] = 0ull; }

#pragma unroll 2
    for (int k4 = 0; k4 < 64; k4++) {
        float4 a0 = A0[k4];
        float4 a1 = A1[k4];
#pragma unroll
        for (int kk = 0; kk < 4; kk++) {
            float av0 = (kk == 0) ? a0.x : (kk == 1) ? a0.y : (kk == 2) ? a0.z : a0.w;
            float av1 = (kk == 0) ? a1.x : (kk == 1) ? a1.y : (kk == 2) ? a1.z : a1.w;
            unsigned long long pa0 = bcast2(av0);
            unsigned long long pa1 = bcast2(av1);
            const unsigned long long* wk = Wq + (size_t)(k4 * 4 + kk) * 24;
            ulonglong2 wA = *(const ulonglong2*)(wk + 0);
            ulonglong2 wB = *(const ulonglong2*)(wk + 2);
            ulonglong2 wC = *(const ulonglong2*)(wk + 4);
            FMA2(c0[0], pa0, wA.x); FMA2(c0[1], pa0, wA.y);
            FMA2(c0[2], pa0, wB.x); FMA2(c0[3], pa0, wB.y);
            FMA2(c0[4], pa0, wC.x); FMA2(c0[5], pa0, wC.y);
            FMA2(c1[0], pa1, wA.x); FMA2(c1[1], pa1, wA.y);
            FMA2(c1[2], pa1, wB.x); FMA2(c1[3], pa1, wB.y);
            FMA2(c1[4], pa1, wC.x); FMA2(c1[5], pa1, wC.y);
        }
    }

    float bias[12];
#pragma unroll
    for (int j = 0; j < 12; j++) bias[j] = fcb[q * 12 + j];

    if (v0) {
        float r[12];
#pragma unroll
        for (int j = 0; j < 6; j++) {
            float2 u = unpk2(c0[j]);
            r[2 * j] = u.x + bias[2 * j];
            r[2 * j + 1] = u.y + bias[2 * j + 1];
        }
        float4* o = (float4*)(g_P + (size_t)row0 * NC + q * 12);
        o[0] = make_float4(r[0], r[1], r[2], r[3]);
        o[1] = make_float4(r[4], r[5], r[6], r[7]);
        o[2] = make_float4(r[8], r[9], r[10], r[11]);
    }
    if (v1) {
        float r[12];
#pragma unroll
        for (int j = 0; j < 6; j++) {
            float2 u = unpk2(c1[j]);
            r[2 * j] = u.x + bias[2 * j];
            r[2 * j + 1] = u.y + bias[2 * j + 1];
        }
        float4* o = (float4*)(g_P + (size_t)row1 * NC + q * 12);
        o[0] = make_float4(r[0], r[1], r[2], r[3]);
        o[1] = make_float4(r[4], r[5], r[6], r[7]);
        o[2] = make_float4(r[8], r[9], r[10], r[11]);
    }
}

// ---------------------------------------------------------------------------
// K2: warp-synchronous CRF scan. grid=128 (dir, b). 128 threads:
//   warp 0: scan — p as 24 packed u64 pairs replicated per lane; lane l<24
//           computes outputs (2l,2l+1) via pairwise-packed FMA2; exchange via
//           __shfl_sync u64. NO barriers/smem traffic in the loop.
//   warps 1-3: stage es/logits; warps 2-3: numerator. One barrier after.
// ---------------------------------------------------------------------------
__global__ __launch_bounds__(128, 1)
void k_crf2(const int* __restrict__ x, const int* __restrict__ lab,
            const float* __restrict__ st, const float* __restrict__ en,
            const float* __restrict__ tr, float* __restrict__ logits,
            float* __restrict__ loss_out) {
    extern __shared__ __align__(16) float sm[];
    float* bd = sm;                    // [64] boundary (st or en), padded
    float* es = sm + 64;               // [HT][NC] raw emissions
    int*   xs = (int*)(es + HT * NC);  // [HT]
    __shared__ float rn[2];
    __shared__ unsigned rank;

    const int tid  = threadIdx.x;
    const int wid  = tid >> 5;
    const int lane = tid & 31;
    const int dir  = blockIdx.x & 1;
    const int b    = blockIdx.x >> 1;
    const int base = b * NT;
    float4* lg4 = (float4*)(logits + (size_t)base * NC);
    const float4* P4 = (const float4*)g_P;

    if (tid < NC) bd[tid] = dir ? en[tid] : st[tid];
    for (int s = tid; s < HT; s += 128)
        xs[s] = x[base + (dir ? NT - 1 - s : s)];
    __syncthreads();   // xs, bd ready

    // warp 0 loads M into registers while warps 1-3 stage emissions+logits.
    // M[r][c]: fwd = W[c][r], bwd = W[r][c];  W = exp(tr - log48).
    // m0[j] = (M[r0][2j], M[r0][2j+1]),  m1[j] same for r1.
    unsigned long long m0[24], m1[24];
    if (wid == 0) {
        const int r0 = (lane < 24) ? 2 * lane : 0;
        const int r1 = r0 + 1;
#pragma unroll 4
        for (int j = 0; j < 24; j++) {
            if (dir == 0) {
                m0[j] = pack2(__expf(tr[(2 * j) * NC + r0] - LOG48),
                              __expf(tr[(2 * j + 1) * NC + r0] - LOG48));
                m1[j] = pack2(__expf(tr[(2 * j) * NC + r1] - LOG48),
                              __expf(tr[(2 * j + 1) * NC + r1] - LOG48));
            } else {
                m0[j] = pack2(__expf(tr[r0 * NC + 2 * j] - LOG48),
                              __expf(tr[r0 * NC + 2 * j + 1] - LOG48));
                m1[j] = pack2(__expf(tr[r1 * NC + 2 * j] - LOG48),
                              __expf(tr[r1 * NC + 2 * j + 1] - LOG48));
            }
        }
    } else {
        const int stid = tid - 32;     // 0..95
        float4* es4 = (float4*)es;
        for (int idx = stid; idx < HT * 12; idx += 96) {
            int s = idx / 12, j = idx - s * 12;
            float4 v = P4[(size_t)xs[s] * 12 + j];
            es4[idx] = v;
            int tok = dir ? (NT - 1 - s) : s;
            lg4[tok * 12 + j] = v;
        }
    }
    __syncthreads();   // es ready

    if (wid == 0) {
        // ---- scan: 511 steps, warp-internal only ----
        unsigned long long p[24];
#pragma unroll 4
        for (int j = 0; j < 24; j++)
            p[j] = pack2(__expf(es[2 * j] + bd[2 * j]),
                         __expf(es[2 * j + 1] + bd[2 * j + 1]));
        const float2* es2 = (const float2*)es;
        float2 ep = es2[24 + lane];         // step-1 emission pair (prefetch)
#pragma unroll 1
        for (int s = 1; s < HT; s++) {
            float ex = __expf(ep.x);
            float ey = __expf(ep.y);
            int sn = (s + 1 < HT) ? (s + 1) : s;
            ep = es2[sn * 24 + lane];       // prefetch next (no sync needed)
            unsigned long long e2 = pack2(ex, ey);
            unsigned long long A0 = 0ull, B0 = 0ull, C0 = 0ull;
            unsigned long long A1 = 0ull, B1 = 0ull, C1 = 0ull;
#pragma unroll
            for (int j = 0; j < 8; j++) {
                FMA2(A0, p[j], m0[j]);           FMA2(A1, p[j], m1[j]);
                FMA2(B0, p[j + 8], m0[j + 8]);   FMA2(B1, p[j + 8], m1[j + 8]);
                FMA2(C0, p[j + 16], m0[j + 16]); FMA2(C1, p[j + 16], m1[j + 16]);
            }
            ADD2(A0, B0); ADD2(A0, C0);
            ADD2(A1, B1); ADD2(A1, C1);
            unsigned long long outp = pack2(hadd2(A0), hadd2(A1));
            MUL2(outp, outp, e2);
#pragma unroll
            for (int j = 0; j < 24; j++)
                p[j] = __shfl_sync(0xffffffffu, outp, j);
        }
        // ---- write alpha_mid / beta_mid ----
        if (dir == 0) {
            if (lane < 24) {
                float2 u = unpk2(p[lane]);
                g_ab[0][b][2 * lane] = u.x;
                g_ab[0][b][2 * lane + 1] = u.y;
            }
        } else {
            // beta_mid = M * g_511 (bare matvec, no emission)
            unsigned long long A0 = 0ull, B0 = 0ull, C0 = 0ull;
            unsigned long long A1 = 0ull, B1 = 0ull, C1 = 0ull;
#pragma unroll
            for (int j = 0; j < 8; j++) {
                FMA2(A0, p[j], m0[j]);           FMA2(A1, p[j], m1[j]);
                FMA2(B0, p[j + 8], m0[j + 8]);   FMA2(B1, p[j + 8], m1[j + 8]);
                FMA2(C0, p[j + 16], m0[j + 16]); FMA2(C1, p[j + 16], m1[j + 16]);
            }
            ADD2(A0, B0); ADD2(A0, C0);
            ADD2(A1, B1); ADD2(A1, C1);
            if (lane < 24) {
                g_ab[1][b][2 * lane] = hadd2(A0);
                g_ab[1][b][2 * lane + 1] = hadd2(A1);
            }
        }
    } else if (tid >= 64) {
        // ---- numerator half (warps 2-3, concurrent with the scan) ----
        const int nid = tid - 64;      // 0..63
        float np = 0.f;
        for (int s = nid; s < HT; s += 64) {
            int t = dir ? (HT + s) : s;
            int es_idx = dir ? (511 - s) : s;
            np += es[es_idx * NC + lab[base + t]];
            int tp = dir ? (511 + s) : s;
            if (dir || tp < 511)
                np += tr[lab[base + tp] * NC + lab[base + tp + 1]];
        }
        if (nid == 0) np += dir ? en[lab[base + NT - 1]] : st[lab[base]];
#pragma unroll
        for (int o = 16; o; o >>= 1) np += __shfl_down_sync(0xffffffffu, np, o);
        if (lane == 0) rn[wid - 2] = np;
    }
    __syncthreads();

    if (tid == 0) {
        g_num[blockIdx.x] = rn[0] + rn[1];
        __threadfence();
        rank = atomicAdd(&g_ctr, 1u);
    }
    __syncthreads();

    if (rank == 2 * NB - 1) {          // last block combines the loss
        __threadfence();
        float v = 0.f;
        if (tid < NB) {
            float dot = 0.f;
#pragma unroll 8
            for (int c = 0; c < NC; c++) dot += g_ab[0][tid][c] * g_ab[1][tid][c];
            v = g_num[2 * tid] + g_num[2 * tid + 1] - (logf(dot) + T1_LOG48);
        }
#pragma unroll
        for (int o = 16; o; o >>= 1) v += __shfl_down_sync(0xffffffffu, v, o);
        __shared__ float rr[2];
        if (lane == 0 && wid < 2) rr[wid] = v;
        __syncthreads();
        if (tid == 0) {
            loss_out[0] = -(rr[0] + rr[1]);
            g_ctr = 0u;                // reset for next graph replay
        }
    }
}

// ---------------------------------------------------------------------------
extern "C" void kernel_launch(void* const* d_in, const int* in_sizes, int n_in,
                              void* d_out, int out_size) {
    const int*   x    = (const int*)d_in[0];
    const int*   lab  = (const int*)d_in[1];
    const float* emb  = (const float*)d_in[2];
    const float* fcw  = (const float*)d_in[3];
    const float* fcb  = (const float*)d_in[4];
    const float* strt = (const float*)d_in[5];
    const float* endt = (const float*)d_in[6];
    const float* trns = (const float*)d_in[7];
    float* out = (float*)d_out;

    size_t smem = (size_t)(64 + HT * NC) * sizeof(float) + HT * sizeof(int);
    static int smem_set = 0;
    if (!smem_set) {
        cudaFuncSetAttribute(k_crf2, cudaFuncAttributeMaxDynamicSharedMemorySize,
                             (int)smem);
        smem_set = 1;
    }

    k_gemm<<<(NV + 127) / 128, 256>>>(emb, fcw, fcb);
    k_crf2<<<2 * NB, 128, smem>>>(x, lab, strt, endt, trns, out, out + (out_size - 1));
}

// round 12
// speedup vs baseline: 1.0822x; 1.0822x over previous
#include <cuda_runtime.h>
#include <math.h>

#define NV 50257
#define NE 256
#define NC 48
#define NB 64
#define NT 1024
#define HT 512
#define CH 64                 /* tokens per producer chunk */
#define NCHUNK (HT / CH)      /* 8 */

#define LOG48    3.8712010109078911f
#define T1_LOG48 3960.2386341588226f   /* 1023 * log(48) */

// packed f32x2 helpers (Blackwell: fma/add .rn.f32x2, 64-bit regs)
#define FMA2(acc, a, b) asm("fma.rn.f32x2 %0, %1, %2, %0;" : "+l"(acc) : "l"(a), "l"(b))
#define ADD2(a, b)      asm("add.rn.f32x2 %0, %0, %1;"     : "+l"(a)   : "l"(b))
#define BAR_SCAN()  asm volatile("bar.sync 1, 64;"  ::: "memory")
#define BAR_PROD()  asm volatile("bar.sync 2, 192;" ::: "memory")
__device__ __forceinline__ unsigned long long pack2(float lo, float hi) {
    unsigned long long r;
    asm("mov.b64 %0, {%1, %2};" : "=l"(r) : "r"(__float_as_uint(lo)), "r"(__float_as_uint(hi)));
    return r;
}
__device__ __forceinline__ unsigned long long bcast2(float v) {
    unsigned long long r;
    asm("mov.b64 %0, {%1, %1};" : "=l"(r) : "r"(__float_as_uint(v)));
    return r;
}
__device__ __forceinline__ float hadd2(unsigned long long a) {
    unsigned lo, hi;
    asm("mov.b64 {%0, %1}, %2;" : "=r"(lo), "=r"(hi) : "l"(a));
    return __uint_as_float(lo) + __uint_as_float(hi);
}
__device__ __forceinline__ float2 unpk2(unsigned long long a) {
    unsigned lo, hi;
    asm("mov.b64 {%0, %1}, %2;" : "=r"(lo), "=r"(hi) : "l"(a));
    return make_float2(__uint_as_float(lo), __uint_as_float(hi));
}

// Scratch (static device globals — no runtime allocation)
__device__ float g_ab[2][NB][NC];     // [0]=alpha_mid (fwd), [1]=beta_mid (bwd)
__device__ float g_num[2 * NB];       // per-block partial numerator
__device__ unsigned g_ctr;            // completion counter (reset by last block)

// packed 48-dot: sum_c p[c]*w[c]; p = 12 x ulonglong2 (16B-aligned smem),
// w = 24 packed u64 where wp[m] holds classes (2m, 2m+1). 24 FMA2, 6 chains.
__device__ __forceinline__ float dot48(const float* p, const unsigned long long* wp) {
    const ulonglong2* p2 = (const ulonglong2*)p;
    unsigned long long a0 = 0ull, a1 = 0ull, a2 = 0ull,
                       a3 = 0ull, a4 = 0ull, a5 = 0ull;
#pragma unroll
    for (int j = 0; j < 12; j += 3) {
        ulonglong2 v0 = p2[j], v1 = p2[j + 1], v2 = p2[j + 2];
        FMA2(a0, v0.x, wp[2 * j + 0]); FMA2(a1, v0.y, wp[2 * j + 1]);
        FMA2(a2, v1.x, wp[2 * j + 2]); FMA2(a3, v1.y, wp[2 * j + 3]);
        FMA2(a4, v2.x, wp[2 * j + 4]); FMA2(a5, v2.y, wp[2 * j + 5]);
    }
    ADD2(a0, a3); ADD2(a1, a4); ADD2(a2, a5);
    ADD2(a0, a1); ADD2(a0, a2);
    return hadd2(a0);
}

// ---------------------------------------------------------------------------
// Single fused kernel. grid = 128 (dir = bid&1, b = bid>>1), 256 threads.
//   warps 0-1 (tid 0-63):  serial scan (R8 structure; named bar 1).
//   warps 2-7 (tid 64-255): emission producers — compute P rows for this
//     block's 512 tokens directly from emb/fc_w into smem es + logits,
//     in CH-token chunks gated by s_ready (named bar 2); then numerator.
// Scan gates on s_ready; producers outpace it ~4x after startup.
// ---------------------------------------------------------------------------
__global__ __launch_bounds__(256, 1)
void k_crf(const int* __restrict__ x, const int* __restrict__ lab,
           const float* __restrict__ emb, const float* __restrict__ fcw,
           const float* __restrict__ fcb, const float* __restrict__ st,
           const float* __restrict__ en, const float* __restrict__ tr,
           float* __restrict__ logits, float* __restrict__ loss_out) {
    extern __shared__ __align__(16) float sm[];
    float* pbuf0 = sm;                   // 48
    float* pbuf1 = sm + 48;              // 48
    float* bd    = sm + 96;              // 64 (boundary st/en)
    float* fb    = sm + 160;             // 64 (bias)
    float* Ws    = sm + 224;             // [NE*NC] k-major fc_w
    float* es    = sm + 224 + NE * NC;   // [HT*NC] raw emissions
    int*   xs    = (int*)(es + HT * NC); // [HT]
    __shared__ float s_np;
    __shared__ unsigned rank;
    __shared__ int s_ready;

    const int tid  = threadIdx.x;
    const int wid  = tid >> 5;
    const int lane = tid & 31;
    const int dir  = blockIdx.x & 1;
    const int b    = blockIdx.x >> 1;
    const int base = b * NT;
    float4* lg4 = (float4*)(logits + (size_t)base * NC);

    if (tid == 0) { s_np = 0.f; s_ready = 0; }
    if (tid < NC) bd[tid] = dir ? en[tid] : st[tid];
    for (int s = tid; s < HT; s += 256)
        xs[s] = x[base + (dir ? NT - 1 - s : s)];
    __syncthreads();

    if (tid < 64) {
        // ==================== scan group (warps 0-1) =====================
        const int ci = (tid < NC) ? tid : 0;
        unsigned long long wp[24];
#pragma unroll
        for (int m = 0; m < 24; m++) wp[m] = 0ull;
        if (tid < NC) {
            if (dir == 0) {   // fwd: owns column tid; sum over rows c
#pragma unroll 4
                for (int m = 0; m < 24; m++)
                    wp[m] = pack2(__expf(tr[(2 * m) * NC + tid] - LOG48),
                                  __expf(tr[(2 * m + 1) * NC + tid] - LOG48));
            } else {          // bwd: owns row tid; sum over cols c
#pragma unroll 4
                for (int m = 0; m < 24; m++)
                    wp[m] = pack2(__expf(tr[tid * NC + 2 * m] - LOG48),
                                  __expf(tr[tid * NC + 2 * m + 1] - LOG48));
            }
        }

        int lr = *(volatile int*)&s_ready;
        while (lr < 2) lr = *(volatile int*)&s_ready;

        if (tid < NC) pbuf0[tid] = __expf(es[ci] + bd[ci]);
        float e_nxt = __expf(es[NC + ci]);          // row 1
        BAR_SCAN();

#pragma unroll 1
        for (int s = 1; s + 1 < HT; s += 2) {
            int need = s + 3; if (need > HT) need = HT;
            while (lr < need) lr = *(volatile int*)&s_ready;
            // step s: pbuf0 -> pbuf1
            float e0 = e_nxt;
            float e1 = __expf(es[(s + 1) * NC + ci]);
            float pn0 = dot48(pbuf0, wp) * e0;
            if (tid < NC) pbuf1[tid] = pn0;
            BAR_SCAN();
            // step s+1: pbuf1 -> pbuf0
            e_nxt = (s + 2 < HT) ? __expf(es[(s + 2) * NC + ci]) : 0.f;
            float pn1 = dot48(pbuf1, wp) * e1;
            if (tid < NC) pbuf0[tid] = pn1;
            BAR_SCAN();
        }
        // tail step 511: pbuf0 -> pbuf1 (e_nxt holds exp(es[511]))
        {
            float pn = dot48(pbuf0, wp) * e_nxt;
            if (tid < NC) pbuf1[tid] = pn;
            BAR_SCAN();
        }

        float outv;
        if (dir == 1) outv = dot48(pbuf1, wp);   // beta_mid = (W g_511)/48
        else          outv = (tid < NC) ? pbuf1[tid] : 0.f;
        if (tid < NC) g_ab[dir][b][tid] = outv;
    } else {
        // =================== producer group (warps 2-7) ==================
        const int ptid = tid - 64;    // 0..191
        // stage W transposed (k-major) + bias
        for (int idx = ptid; idx < NC * NE; idx += 192) {
            int c = idx >> 8, k = idx & 255;
            Ws[k * NC + c] = fcw[idx];
        }
        if (ptid < NC) fb[ptid] = fcb[ptid];
        BAR_PROD();

        for (int ch = 0; ch < NCHUNK; ch++) {
            for (int slot = ptid; slot < CH * 4; slot += 192) {
                int s = ch * CH + (slot >> 2);
                int q = slot & 3;
                int row = xs[s];
                const float4* A = (const float4*)emb + (size_t)row * 64;
                const unsigned long long* Wq = (const unsigned long long*)Ws + q * 6;
                unsigned long long acc[6];
#pragma unroll
                for (int j = 0; j < 6; j++) acc[j] = 0ull;
#pragma unroll 2
                for (int k4 = 0; k4 < 64; k4++) {
                    float4 a = A[k4];
#pragma unroll
                    for (int kk = 0; kk < 4; kk++) {
                        float av = (kk == 0) ? a.x : (kk == 1) ? a.y
                                 : (kk == 2) ? a.z : a.w;
                        unsigned long long pa = bcast2(av);
                        const unsigned long long* wk = Wq + (size_t)(k4 * 4 + kk) * 24;
                        ulonglong2 wA = *(const ulonglong2*)(wk + 0);
                        ulonglong2 wB = *(const ulonglong2*)(wk + 2);
                        ulonglong2 wC = *(const ulonglong2*)(wk + 4);
                        FMA2(acc[0], pa, wA.x); FMA2(acc[1], pa, wA.y);
                        FMA2(acc[2], pa, wB.x); FMA2(acc[3], pa, wB.y);
                        FMA2(acc[4], pa, wC.x); FMA2(acc[5], pa, wC.y);
                    }
                }
                float r[12];
#pragma unroll
                for (int j = 0; j < 6; j++) {
                    float2 u = unpk2(acc[j]);
                    r[2 * j]     = u.x + fb[q * 12 + 2 * j];
                    r[2 * j + 1] = u.y + fb[q * 12 + 2 * j + 1];
                }
                float4 v0 = make_float4(r[0], r[1], r[2], r[3]);
                float4 v1 = make_float4(r[4], r[5], r[6], r[7]);
                float4 v2 = make_float4(r[8], r[9], r[10], r[11]);
                float4* ed = (float4*)es + s * 12 + q * 3;
                ed[0] = v0; ed[1] = v1; ed[2] = v2;
                int tok = dir ? (NT - 1 - s) : s;
                float4* od = lg4 + tok * 12 + q * 3;
                od[0] = v0; od[1] = v1; od[2] = v2;
            }
            BAR_PROD();   // drains all producer STS for this chunk
            if (ptid == 0) {
                __threadfence_block();
                *(volatile int*)&s_ready = (ch + 1) * CH;
            }
        }

        // ---- numerator half (es fully staged) ----
        float np = 0.f;
        for (int s = ptid; s < HT; s += 192) {
            int t = dir ? (HT + s) : s;
            int es_idx = dir ? (511 - s) : s;
            np += es[es_idx * NC + lab[base + t]];
            int tp = dir ? (511 + s) : s;
            if (dir || tp < 511)
                np += tr[lab[base + tp] * NC + lab[base + tp + 1]];
        }
        if (ptid == 0) np += dir ? en[lab[base + NT - 1]] : st[lab[base]];
#pragma unroll
        for (int o = 16; o; o >>= 1) np += __shfl_down_sync(0xffffffffu, np, o);
        if (lane == 0) atomicAdd(&s_np, np);
    }
    __syncthreads();

    if (tid == 0) {
        g_num[blockIdx.x] = s_np;
        __threadfence();
        rank = atomicAdd(&g_ctr, 1u);
    }
    __syncthreads();

    if (rank == 2 * NB - 1) {          // last block combines the loss
        __threadfence();
        float v = 0.f;
        if (tid < NB) {
            float dot = 0.f;
#pragma unroll 8
            for (int c = 0; c < NC; c++) dot += g_ab[0][tid][c] * g_ab[1][tid][c];
            v = g_num[2 * tid] + g_num[2 * tid + 1] - (logf(dot) + T1_LOG48);
        }
#pragma unroll
        for (int o = 16; o; o >>= 1) v += __shfl_down_sync(0xffffffffu, v, o);
        __shared__ float rr[2];
        if (lane == 0 && wid < 2) rr[wid] = v;
        __syncthreads();
        if (tid == 0) {
            loss_out[0] = -(rr[0] + rr[1]);
            g_ctr = 0u;                // reset for next graph replay
        }
    }
}

// ---------------------------------------------------------------------------
extern "C" void kernel_launch(void* const* d_in, const int* in_sizes, int n_in,
                              void* d_out, int out_size) {
    const int*   x    = (const int*)d_in[0];
    const int*   lab  = (const int*)d_in[1];
    const float* emb  = (const float*)d_in[2];
    const float* fcw  = (const float*)d_in[3];
    const float* fcb  = (const float*)d_in[4];
    const float* strt = (const float*)d_in[5];
    const float* endt = (const float*)d_in[6];
    const float* trns = (const float*)d_in[7];
    float* out = (float*)d_out;

    size_t smem = (size_t)(224 + NE * NC + HT * NC) * sizeof(float) + HT * sizeof(int);
    static int smem_set = 0;
    if (!smem_set) {
        cudaFuncSetAttribute(k_crf, cudaFuncAttributeMaxDynamicSharedMemorySize,
                             (int)smem);
        smem_set = 1;
    }

    k_crf<<<2 * NB, 256, smem>>>(x, lab, emb, fcw, fcb, strt, endt, trns,
                                 out, out + (out_size - 1));
}

// round 13
// speedup vs baseline: 1.0874x; 1.0048x over previous
#include <cuda_runtime.h>
#include <math.h>

#define NV 50257
#define NE 256
#define NC 48
#define NB 64
#define NT 1024
#define HT 512
#define CH 64                 /* tokens per producer chunk */
#define NCHUNK (HT / CH)      /* 8 */

#define LOG48    3.8712010109078911f
#define T1_LOG48 3960.2386341588226f   /* 1023 * log(48) */

// packed f32x2 helpers (Blackwell: fma/add .rn.f32x2, 64-bit regs)
#define FMA2(acc, a, b) asm("fma.rn.f32x2 %0, %1, %2, %0;" : "+l"(acc) : "l"(a), "l"(b))
#define ADD2(a, b)      asm("add.rn.f32x2 %0, %0, %1;"     : "+l"(a)   : "l"(b))
#define BAR_SCAN()  asm volatile("bar.sync 1, 64;"  ::: "memory")
#define BAR_PROD()  asm volatile("bar.sync 2, 128;" ::: "memory")
__device__ __forceinline__ unsigned long long pack2(float lo, float hi) {
    unsigned long long r;
    asm("mov.b64 %0, {%1, %2};" : "=l"(r) : "r"(__float_as_uint(lo)), "r"(__float_as_uint(hi)));
    return r;
}
__device__ __forceinline__ unsigned long long bcast2(float v) {
    unsigned long long r;
    asm("mov.b64 %0, {%1, %1};" : "=l"(r) : "r"(__float_as_uint(v)));
    return r;
}
__device__ __forceinline__ float hadd2(unsigned long long a) {
    unsigned lo, hi;
    asm("mov.b64 {%0, %1}, %2;" : "=r"(lo), "=r"(hi) : "l"(a));
    return __uint_as_float(lo) + __uint_as_float(hi);
}
__device__ __forceinline__ float2 unpk2(unsigned long long a) {
    unsigned lo, hi;
    asm("mov.b64 {%0, %1}, %2;" : "=r"(lo), "=r"(hi) : "l"(a));
    return make_float2(__uint_as_float(lo), __uint_as_float(hi));
}

// Scratch (static device globals — no runtime allocation)
__device__ float g_ab[2][NB][NC];     // [0]=alpha_mid (fwd), [1]=beta_mid (bwd)
__device__ float g_num[2 * NB];       // per-block partial numerator
__device__ unsigned g_ctr;            // completion counter (reset by last block)

// packed 48-dot: sum_c p[c]*w[c]; p = 12 x ulonglong2 (16B-aligned smem),
// w = 24 packed u64 where wp[m] holds classes (2m, 2m+1). 24 FMA2, 6 chains.
__device__ __forceinline__ float dot48(const float* p, const unsigned long long* wp) {
    const ulonglong2* p2 = (const ulonglong2*)p;
    unsigned long long a0 = 0ull, a1 = 0ull, a2 = 0ull,
                       a3 = 0ull, a4 = 0ull, a5 = 0ull;
#pragma unroll
    for (int j = 0; j < 12; j += 3) {
        ulonglong2 v0 = p2[j], v1 = p2[j + 1], v2 = p2[j + 2];
        FMA2(a0, v0.x, wp[2 * j + 0]); FMA2(a1, v0.y, wp[2 * j + 1]);
        FMA2(a2, v1.x, wp[2 * j + 2]); FMA2(a3, v1.y, wp[2 * j + 3]);
        FMA2(a4, v2.x, wp[2 * j + 4]); FMA2(a5, v2.y, wp[2 * j + 5]);
    }
    ADD2(a0, a3); ADD2(a1, a4); ADD2(a2, a5);
    ADD2(a0, a1); ADD2(a0, a2);
    return hadd2(a0);
}

// ---------------------------------------------------------------------------
// Single fused kernel. grid = 128 (dir = bid&1, b = bid>>1), 256 threads.
//   warps 0-1  (SMSP 0,1): serial scan — EXCLUSIVE owners of SMSP 0,1.
//   warps 2,3,6,7 (SMSP 2,3): emission producers (P rows -> smem es +
//     logits, CH-token chunks gated by s_ready), then numerator.
//   warps 4,5  (SMSP 0,1): sleep at the final barrier (BAR-blocked warps
//     issue nothing — keeps SMSP 0,1 clean for the scan).
// ---------------------------------------------------------------------------
__global__ __launch_bounds__(256, 1)
void k_crf(const int* __restrict__ x, const int* __restrict__ lab,
           const float* __restrict__ emb, const float* __restrict__ fcw,
           const float* __restrict__ fcb, const float* __restrict__ st,
           const float* __restrict__ en, const float* __restrict__ tr,
           float* __restrict__ logits, float* __restrict__ loss_out) {
    extern __shared__ __align__(16) float sm[];
    float* pbuf0 = sm;                   // 48
    float* pbuf1 = sm + 48;              // 48
    float* bd    = sm + 96;              // 64 (boundary st/en)
    float* fb    = sm + 160;             // 64 (bias)
    float* Ws    = sm + 224;             // [NE*NC] k-major fc_w
    float* es    = sm + 224 + NE * NC;   // [HT*NC] raw emissions
    int*   xs    = (int*)(es + HT * NC); // [HT]
    __shared__ float s_np;
    __shared__ unsigned rank;
    __shared__ int s_ready;

    const int tid  = threadIdx.x;
    const int wid  = tid >> 5;
    const int lane = tid & 31;
    const int dir  = blockIdx.x & 1;
    const int b    = blockIdx.x >> 1;
    const int base = b * NT;
    float4* lg4 = (float4*)(logits + (size_t)base * NC);

    if (tid == 0) { s_np = 0.f; s_ready = 0; }
    if (tid < NC) bd[tid] = dir ? en[tid] : st[tid];
    for (int s = tid; s < HT; s += 256)
        xs[s] = x[base + (dir ? NT - 1 - s : s)];
    __syncthreads();

    const bool is_scan = (wid < 2);
    const bool is_prod = (wid == 2) || (wid == 3) || (wid == 6) || (wid == 7);

    if (is_scan) {
        // ==================== scan group (warps 0-1, SMSP 0,1) ===========
        const int ci = (tid < NC) ? tid : 0;
        unsigned long long wp[24];
#pragma unroll
        for (int m = 0; m < 24; m++) wp[m] = 0ull;
        if (tid < NC) {
            if (dir == 0) {   // fwd: owns column tid; sum over rows c
#pragma unroll 4
                for (int m = 0; m < 24; m++)
                    wp[m] = pack2(__expf(tr[(2 * m) * NC + tid] - LOG48),
                                  __expf(tr[(2 * m + 1) * NC + tid] - LOG48));
            } else {          // bwd: owns row tid; sum over cols c
#pragma unroll 4
                for (int m = 0; m < 24; m++)
                    wp[m] = pack2(__expf(tr[tid * NC + 2 * m] - LOG48),
                                  __expf(tr[tid * NC + 2 * m + 1] - LOG48));
            }
        }

        int lr = *(volatile int*)&s_ready;
        while (lr < 2) lr = *(volatile int*)&s_ready;

        if (tid < NC) pbuf0[tid] = __expf(es[ci] + bd[ci]);
        float e_nxt = __expf(es[NC + ci]);          // row 1
        BAR_SCAN();

#pragma unroll 1
        for (int s = 1; s + 1 < HT; s += 2) {
            int need = s + 3; if (need > HT) need = HT;
            while (lr < need) lr = *(volatile int*)&s_ready;
            // step s: pbuf0 -> pbuf1
            float e0 = e_nxt;
            float e1 = __expf(es[(s + 1) * NC + ci]);
            float pn0 = dot48(pbuf0, wp) * e0;
            if (tid < NC) pbuf1[tid] = pn0;
            BAR_SCAN();
            // step s+1: pbuf1 -> pbuf0
            e_nxt = (s + 2 < HT) ? __expf(es[(s + 2) * NC + ci]) : 0.f;
            float pn1 = dot48(pbuf1, wp) * e1;
            if (tid < NC) pbuf0[tid] = pn1;
            BAR_SCAN();
        }
        // tail step 511: pbuf0 -> pbuf1 (e_nxt holds exp(es[511]))
        {
            float pn = dot48(pbuf0, wp) * e_nxt;
            if (tid < NC) pbuf1[tid] = pn;
            BAR_SCAN();
        }

        float outv;
        if (dir == 1) outv = dot48(pbuf1, wp);   // beta_mid = (W g_511)/48
        else          outv = (tid < NC) ? pbuf1[tid] : 0.f;
        if (tid < NC) g_ab[dir][b][tid] = outv;
    } else if (is_prod) {
        // ============ producer group (warps 2,3,6,7 -> SMSP 2,3) =========
        const int ptid = (tid < 128) ? (tid - 64) : (tid - 128);   // 0..127
        // stage W transposed (k-major) + bias
        for (int idx = ptid; idx < NC * NE; idx += 128) {
            int c = idx >> 8, k = idx & 255;
            Ws[k * NC + c] = fcw[idx];
        }
        if (ptid < NC) fb[ptid] = fcb[ptid];
        BAR_PROD();

        for (int ch = 0; ch < NCHUNK; ch++) {
#pragma unroll
            for (int half = 0; half < 2; half++) {
                int slot = ptid + half * 128;          // 0..255
                int s = ch * CH + (slot >> 2);
                int q = slot & 3;
                int row = xs[s];
                const float4* A = (const float4*)emb + (size_t)row * 64;
                const unsigned long long* Wq = (const unsigned long long*)Ws + q * 6;
                unsigned long long acc[6];
#pragma unroll
                for (int j = 0; j < 6; j++) acc[j] = 0ull;
#pragma unroll 2
                for (int k4 = 0; k4 < 64; k4++) {
                    float4 a = A[k4];
#pragma unroll
                    for (int kk = 0; kk < 4; kk++) {
                        float av = (kk == 0) ? a.x : (kk == 1) ? a.y
                                 : (kk == 2) ? a.z : a.w;
                        unsigned long long pa = bcast2(av);
                        const unsigned long long* wk = Wq + (size_t)(k4 * 4 + kk) * 24;
                        ulonglong2 wA = *(const ulonglong2*)(wk + 0);
                        ulonglong2 wB = *(const ulonglong2*)(wk + 2);
                        ulonglong2 wC = *(const ulonglong2*)(wk + 4);
                        FMA2(acc[0], pa, wA.x); FMA2(acc[1], pa, wA.y);
                        FMA2(acc[2], pa, wB.x); FMA2(acc[3], pa, wB.y);
                        FMA2(acc[4], pa, wC.x); FMA2(acc[5], pa, wC.y);
                    }
                }
                float r[12];
#pragma unroll
                for (int j = 0; j < 6; j++) {
                    float2 u = unpk2(acc[j]);
                    r[2 * j]     = u.x + fb[q * 12 + 2 * j];
                    r[2 * j + 1] = u.y + fb[q * 12 + 2 * j + 1];
                }
                float4 v0 = make_float4(r[0], r[1], r[2], r[3]);
                float4 v1 = make_float4(r[4], r[5], r[6], r[7]);
                float4 v2 = make_float4(r[8], r[9], r[10], r[11]);
                float4* ed = (float4*)es + s * 12 + q * 3;
                ed[0] = v0; ed[1] = v1; ed[2] = v2;
                int tok = dir ? (NT - 1 - s) : s;
                float4* od = lg4 + tok * 12 + q * 3;
                od[0] = v0; od[1] = v1; od[2] = v2;
            }
            BAR_PROD();   // drains all producer STS for this chunk
            if (ptid == 0) {
                __threadfence_block();
                *(volatile int*)&s_ready = (ch + 1) * CH;
            }
        }

        // ---- numerator half (es fully staged) ----
        float np = 0.f;
        for (int s = ptid; s < HT; s += 128) {
            int t = dir ? (HT + s) : s;
            int es_idx = dir ? (511 - s) : s;
            np += es[es_idx * NC + lab[base + t]];
            int tp = dir ? (511 + s) : s;
            if (dir || tp < 511)
                np += tr[lab[base + tp] * NC + lab[base + tp + 1]];
        }
        if (ptid == 0) np += dir ? en[lab[base + NT - 1]] : st[lab[base]];
#pragma unroll
        for (int o = 16; o; o >>= 1) np += __shfl_down_sync(0xffffffffu, np, o);
        if (lane == 0) atomicAdd(&s_np, np);
    }
    // warps 4,5 fall through directly: BAR-blocked here, issuing nothing.
    __syncthreads();

    if (tid == 0) {
        g_num[blockIdx.x] = s_np;
        __threadfence();
        rank = atomicAdd(&g_ctr, 1u);
    }
    __syncthreads();

    if (rank == 2 * NB - 1) {          // last block combines the loss
        __threadfence();
        float v = 0.f;
        if (tid < NB) {
            float dot = 0.f;
#pragma unroll 8
            for (int c = 0; c < NC; c++) dot += g_ab[0][tid][c] * g_ab[1][tid][c];
            v = g_num[2 * tid] + g_num[2 * tid + 1] - (logf(dot) + T1_LOG48);
        }
#pragma unroll
        for (int o = 16; o; o >>= 1) v += __shfl_down_sync(0xffffffffu, v, o);
        __shared__ float rr[2];
        if (lane == 0 && wid < 2) rr[wid] = v;
        __syncthreads();
        if (tid == 0) {
            loss_out[0] = -(rr[0] + rr[1]);
            g_ctr = 0u;                // reset for next graph replay
        }
    }
}

// ---------------------------------------------------------------------------
extern "C" void kernel_launch(void* const* d_in, const int* in_sizes, int n_in,
                              void* d_out, int out_size) {
    const int*   x    = (const int*)d_in[0];
    const int*   lab  = (const int*)d_in[1];
    const float* emb  = (const float*)d_in[2];
    const float* fcw  = (const float*)d_in[3];
    const float* fcb  = (const float*)d_in[4];
    const float* strt = (const float*)d_in[5];
    const float* endt = (const float*)d_in[6];
    const float* trns = (const float*)d_in[7];
    float* out = (float*)d_out;

    size_t smem = (size_t)(224 + NE * NC + HT * NC) * sizeof(float) + HT * sizeof(int);
    static int smem_set = 0;
    if (!smem_set) {
        cudaFuncSetAttribute(k_crf, cudaFuncAttributeMaxDynamicSharedMemorySize,
                             (int)smem);
        smem_set = 1;
    }

    k_crf<<<2 * NB, 256, smem>>>(x, lab, emb, fcw, fcb, strt, endt, trns,
                                 out, out + (out_size - 1));
}